// round 8
// baseline (speedup 1.0000x reference)
#include <cuda_runtime.h>
#include <cuda_fp16.h>
#include <cstdint>

// ---------------- problem constants ----------------
#define BB   64
#define TT   512
#define BT   (BB*TT)          // 32768
#define SKD  256
#define AND_ 96
#define DD   352              // SK+AN
#define HH   256
#define G4   1024             // 4*H
#define ATTD 80
#define NC   2000
#define RES_ELEMS ((size_t)BT*NC)    // 65,536,000
#define SAE_ELEMS ((size_t)BT*DD)    // 11,534,336

typedef unsigned long long u64;

// ---------------- device scratch (static, allowed) ----------------
__device__ __half g_sae_h  [BT*DD];        // 23 MB  (fp16 GEMM A)
__device__ float  g_xg     [BT*G4];        // 134 MB (fp32)
__device__ __half g_hall_h [BT*HH];        // 16.8 MB
__device__ float  g_scores [BT];
__device__ __half g_cum1_h [BT*HH];        // 16.8 MB (exclusive cumsum of attn)
__device__ float  g_hbuf [2][BB][HH];      // ping-pong h state (full fp32)
__device__ int    g_cnt  [8];              // per batch-group barrier counters
// fp16 weight copies
__device__ __half g_wih_h [G4*DD];
__device__ __half g_mlpw_h[ATTD*HH];
__device__ __half g_fcw_h [NC*2*HH];

extern __shared__ float dynsmem[];

// ---------------- helpers ----------------
__device__ __forceinline__ float sigf(float x){ return 1.f/(1.f+__expf(-x)); }
__device__ __forceinline__ void ffma2(u64& d, u64 a, u64 b){
    asm volatile("fma.rn.f32x2 %0, %1, %2, %0;" : "+l"(d) : "l"(a), "l"(b));
}
__device__ __forceinline__ u64 pack1(float x){
    float2 f = make_float2(x, 0.f); return *reinterpret_cast<u64*>(&f);
}
__device__ __forceinline__ float hsum2(u64 v){
    float2 f = *reinterpret_cast<float2*>(&v); return f.x + f.y;
}
__device__ __forceinline__ void cpa16(uint32_t s, const void* g){
    asm volatile("cp.async.cg.shared.global [%0], [%1], 16;\n" :: "r"(s), "l"(g));
}
__device__ __forceinline__ void cpa16z(uint32_t s, const void* g, int ok){
    int bytes = ok ? 16 : 0;
    asm volatile("cp.async.cg.shared.global [%0], [%1], 16, %2;\n"
                 :: "r"(s), "l"(g), "r"(bytes));
}
__device__ __forceinline__ uint32_t smem_u32(const void* p){
    uint32_t a;
    asm("{ .reg .u64 t; cvta.to.shared.u64 t, %1; cvt.u32.u64 %0, t; }"
        : "=r"(a) : "l"(p));
    return a;
}

// ---------------- init: weights->fp16 + hbuf/cnt reset (single launch) ------
__global__ void atkt_init_all(const float* __restrict__ Wih,
                              const float* __restrict__ mlp_w,
                              const float* __restrict__ fc_w){
    int i = blockIdx.x*blockDim.x + threadIdx.x;
    if (i < G4*DD)    g_wih_h[i]  = __float2half_rn(Wih[i]);
    if (i < ATTD*HH)  g_mlpw_h[i] = __float2half_rn(mlp_w[i]);
    if (i < NC*2*HH)  g_fcw_h[i]  = __float2half_rn(fc_w[i]);
    if (i < 2*BB*HH)  ((float*)g_hbuf)[i] = 0.f;
    if (i < 8)        g_cnt[i] = 0;
}

// ---------------- embedding gather + concat ----------------
__global__ void atkt_embed_kernel(const int* __restrict__ skill,
                                  const int* __restrict__ answer,
                                  const float* __restrict__ skill_emb,
                                  const float* __restrict__ answer_emb,
                                  float* __restrict__ out_sae){
    int bt = blockIdx.x;
    int d  = threadIdx.x;            // 0..351
    int ans = answer[bt];
    int sk  = skill[bt];
    float v;
    if (ans == 1) v = (d < SKD) ? skill_emb[sk*SKD + d]
                                : answer_emb[ans*AND_ + (d - SKD)];
    else          v = (d < AND_) ? answer_emb[ans*AND_ + d]
                                 : skill_emb[sk*SKD + (d - AND_)];
    size_t idx = (size_t)bt*DD + d;
    g_sae_h[idx] = __float2half_rn(v);   // GEMM operand
    if (out_sae) out_sae[idx] = v;       // exact output tail
}

// ================= fp16 mma GEMM =================
// C(MxN) = act(A(MxK) * B(NxK)^T + bias1 [+bias2]); A,B fp16, accum f32.
// A may be split at K1: k<K1 from A(lda), k>=K1 from A2(lda2).
// block tile 128x128, K-tile 32, 3-stage cp.async ring, 8 warps (2Mx4N),
// warp tile 64x32, mma m16n8k16. act: 0=none, 1=sigmoid, 2=tanh,
// 3=score (write Cs[row] = sum_cols tanh(x+bias1)*simw; no C write)
#define HSTG 10240
__global__ __launch_bounds__(256, 2)
void atkt_gemm_h(const __half* __restrict__ A, int lda,
                 const __half* __restrict__ A2, int lda2, int K1,
                 const __half* __restrict__ Bm,
                 const float* __restrict__ bias1, const float* __restrict__ bias2,
                 const float* __restrict__ simw,
                 float* __restrict__ C, float* __restrict__ Cs,
                 int M, int N, int K, int act){
    __half* smh = (__half*)dynsmem;          // [3][HSTG] halves
    __shared__ float sc[128];
    const int tid  = threadIdx.x;
    const int lane = tid & 31, warp = tid >> 5;
    const int bm = blockIdx.y * 128, bn = blockIdx.x * 128;
    const int wm = (warp & 1) * 64, wn = (warp >> 1) * 32;
    const uint32_t sm0 = smem_u32(smh);

    float acc[4][4][4];
    #pragma unroll
    for (int i=0;i<4;i++)
      #pragma unroll
      for (int j=0;j<4;j++)
        #pragma unroll
        for (int q=0;q<4;q++) acc[i][j][q]=0.f;

    const int nkt = K >> 5;

    // stage loader: per array 512 x 16B chunks, 2 per thread
    auto load_stage = [&](int s, int kt){
        int kb = kt << 5;
        const __half* Ap; int la, ko;
        if (K1 && kb >= K1){ Ap = A2; la = lda2; ko = kb - K1; }
        else               { Ap = A;  la = lda;  ko = kb; }
        #pragma unroll
        for (int i = 0; i < 2; ++i){
            int idx = tid + (i << 8);        // 0..511
            int row = idx >> 2;
            int c8  = (idx & 3) << 3;        // half col 0,8,16,24
            uint32_t so = sm0 + (uint32_t)s*(HSTG*2) + row*80 + (c8<<1);
            cpa16(so, Ap + (size_t)(bm + row)*la + ko + c8);
            int gn = bn + row;
            int gnc = (gn < N) ? gn : (N - 1);
            cpa16z(so + (HSTG), Bm + (size_t)gnc*K + kb + c8, gn < N);
        }
        asm volatile("cp.async.commit_group;\n");
    };

    load_stage(0, 0);
    if (nkt > 1) load_stage(1, 1);
    for (int kt = 0; kt < nkt; ++kt){
        if (kt == nkt - 1) asm volatile("cp.async.wait_group 0;\n");
        else               asm volatile("cp.async.wait_group 1;\n");
        __syncthreads();
        if (kt + 2 < nkt) load_stage((kt + 2) % 3, kt + 2);
        const int s = kt % 3;
        const uint32_t* a32 = (const uint32_t*)(smh + (size_t)s*HSTG);
        const uint32_t* b32 = a32 + 2560;
        #pragma unroll
        for (int ks = 0; ks < 2; ++ks){
            const int kk2 = ks << 3;               // uint32 col offset (0|8)
            uint32_t af[4][4], bf[4][2];
            #pragma unroll
            for (int ma=0; ma<4; ma++){
                int r = wm + ma*16 + (lane>>2);
                int base = r*20 + kk2 + (lane&3);
                af[ma][0] = a32[base];
                af[ma][1] = a32[base + 8*20];
                af[ma][2] = a32[base + 4];
                af[ma][3] = a32[base + 8*20 + 4];
            }
            #pragma unroll
            for (int na=0; na<4; na++){
                int r = wn + na*8 + (lane>>2);
                int base = r*20 + kk2 + (lane&3);
                bf[na][0] = b32[base];
                bf[na][1] = b32[base + 4];
            }
            #pragma unroll
            for (int ma=0; ma<4; ma++)
                #pragma unroll
                for (int na=0; na<4; na++){
                    asm volatile(
                      "mma.sync.aligned.m16n8k16.row.col.f32.f16.f16.f32 "
                      "{%0,%1,%2,%3}, {%4,%5,%6,%7}, {%8,%9}, {%0,%1,%2,%3};\n"
                      : "+f"(acc[ma][na][0]), "+f"(acc[ma][na][1]),
                        "+f"(acc[ma][na][2]), "+f"(acc[ma][na][3])
                      : "r"(af[ma][0]), "r"(af[ma][1]), "r"(af[ma][2]), "r"(af[ma][3]),
                        "r"(bf[na][0]), "r"(bf[na][1]));
                }
        }
    }

    if (act == 3){
        // fused score: Cs[bm+r] = sum_{cc<N} tanh(acc + bias1[cc]) * simw[cc]
        if (tid < 128) sc[tid] = 0.f;
        __syncthreads();
        float part[4][2];
        #pragma unroll
        for (int ma=0; ma<4; ma++){ part[ma][0]=0.f; part[ma][1]=0.f; }
        #pragma unroll
        for (int ma=0; ma<4; ma++)
            #pragma unroll
            for (int na=0; na<4; na++)
                #pragma unroll
                for (int q=0; q<4; q++){
                    int cc = bn + wn + na*8 + (lane&3)*2 + (q&1);
                    if (cc < N){
                        float x = tanhf(acc[ma][na][q] + bias1[cc]);
                        part[ma][q>>1] += x * simw[cc];
                    }
                }
        #pragma unroll
        for (int ma=0; ma<4; ma++)
            #pragma unroll
            for (int qh=0; qh<2; qh++){
                float v = part[ma][qh];
                v += __shfl_xor_sync(0xffffffffu, v, 1);
                v += __shfl_xor_sync(0xffffffffu, v, 2);
                if ((lane & 3) == 0){
                    int rloc = wm + ma*16 + (lane>>2) + qh*8;
                    atomicAdd(&sc[rloc], v);
                }
            }
        __syncthreads();
        if (tid < 128) Cs[bm + tid] = sc[tid];
        return;
    }

    // epilogue: c0->(r,c) c1->(r,c+1) c2->(r+8,c) c3->(r+8,c+1)
    #pragma unroll
    for (int ma=0; ma<4; ma++){
        int row = bm + wm + ma*16 + (lane>>2);
        #pragma unroll
        for (int na=0; na<4; na++){
            int col = bn + wn + na*8 + (lane&3)*2;
            #pragma unroll
            for (int q=0;q<4;q++){
                int rr = row + ((q>=2) ? 8 : 0);
                int cc = col + (q&1);
                if (cc < N){
                    float x = acc[ma][na][q] + bias1[cc];
                    if (bias2) x += bias2[cc];
                    if (act==1)      x = sigf(x);
                    else if (act==2) x = tanhf(x);
                    C[(size_t)rr*N + cc] = x;
                }
            }
        }
    }
}
#define GEMM_SMEM (3*HSTG*2)   // 61440 bytes

// ---------------- persistent LSTM scan (FFMA2 + xr prefetch) ----------------
// 128 blocks = 8 batch-groups x 16 h-slices, 128 threads each.
__global__ __launch_bounds__(128)
void atkt_lstm_kernel(const float* __restrict__ Whh){
    float* Wsh = dynsmem;                 // [4][16][256] = 64KB
    float* hsh = dynsmem + 4*16*256;      // [8][256]
    const int tid = threadIdx.x;
    const int bg  = blockIdx.x >> 4;
    const int hs  = blockIdx.x & 15;
    const int bl  = tid & 7;
    const int jl  = tid >> 3;
    const int b   = bg*8 + bl;
    const int j   = hs*16 + jl;

    for (int idx = tid; idx < 4*16*256; idx += 128){
        int gate = idx >> 12;
        int jj   = (idx >> 8) & 15;
        int k    = idx & 255;
        Wsh[idx] = Whh[((gate<<8) + (hs<<4) + jj)*256 + k];
    }
    float c = 0.f;
    // prefetch xr for t=0
    const float* xr0 = g_xg + (size_t)(b*TT)*G4;
    float nai = xr0[j], naf = xr0[256+j], nag = xr0[512+j], nao = xr0[768+j];

    for (int t = 0; t < TT; ++t){
        __syncthreads();   // gates on tid0's barrier spin from previous step
        {
            const float4* hsrc = (const float4*)&g_hbuf[t & 1][bg*8][0];
            #pragma unroll
            for (int i = 0; i < 4; ++i){
                int idx = tid + i*128;
                ((float4*)hsh)[idx] = __ldcg(hsrc + idx);
            }
        }
        __syncthreads();
        u64 ai2 = pack1(nai);
        u64 af2 = pack1(naf);
        u64 ag2 = pack1(nag);
        u64 ao2 = pack1(nao);
        const ulonglong2* hv = (const ulonglong2*)&hsh[bl*256];
        const ulonglong2* wi = (const ulonglong2*)&Wsh[(0*16 + jl)*256];
        const ulonglong2* wf = (const ulonglong2*)&Wsh[(1*16 + jl)*256];
        const ulonglong2* wg = (const ulonglong2*)&Wsh[(2*16 + jl)*256];
        const ulonglong2* wo = (const ulonglong2*)&Wsh[(3*16 + jl)*256];
        #pragma unroll 8
        for (int k4 = 0; k4 < 64; ++k4){
            ulonglong2 h2 = hv[k4];
            ulonglong2 w;
            w = wi[k4]; ffma2(ai2, h2.x, w.x); ffma2(ai2, h2.y, w.y);
            w = wf[k4]; ffma2(af2, h2.x, w.x); ffma2(af2, h2.y, w.y);
            w = wg[k4]; ffma2(ag2, h2.x, w.x); ffma2(ag2, h2.y, w.y);
            w = wo[k4]; ffma2(ao2, h2.x, w.x); ffma2(ao2, h2.y, w.y);
        }
        float ai = hsum2(ai2), af = hsum2(af2), ag = hsum2(ag2), ao = hsum2(ao2);
        c = sigf(af)*c + sigf(ai)*tanhf(ag);
        float h = sigf(ao)*tanhf(c);
        const int bt = b*TT + t;
        g_hall_h[(size_t)bt*HH + j] = __float2half_rn(h);
        __stcg(&g_hbuf[(t+1)&1][b][j], h);
        // prefetch xr for t+1 (overlaps with barrier spin below)
        if (t + 1 < TT){
            const float* xr = g_xg + (size_t)(bt + 1)*G4;
            nai = __ldcg(xr + j);
            naf = __ldcg(xr + 256 + j);
            nag = __ldcg(xr + 512 + j);
            nao = __ldcg(xr + 768 + j);
        }
        __syncthreads();
        if (tid == 0){
            __threadfence();                 // release CTA stores at gpu scope
            atomicAdd(&g_cnt[bg], 1);
            int tgt = 16*(t+1);
            int v;
            do {
                asm volatile("ld.global.relaxed.gpu.s32 %0, [%1];"
                             : "=r"(v) : "l"(&g_cnt[bg]) : "memory");
            } while (v < tgt);
            asm volatile("fence.acq_rel.gpu;" ::: "memory");  // acquire once
        }
    }
}

// ---------------- causal attention + exclusive cumsum -> g_cum1_h -----------
// 128 blocks = 64 batches x 2 halves of the H dim.
__global__ void atkt_attn_kernel(){
    const int b   = blockIdx.x >> 1;
    const int j   = ((blockIdx.x & 1) << 7) + threadIdx.x;
    const int tid = threadIdx.x;
    __shared__ float e_sh[TT];
    __shared__ float red[128];
    float m = -1e30f;
    for (int t = tid; t < TT; t += 128) m = fmaxf(m, g_scores[b*TT + t]);
    red[tid] = m; __syncthreads();
    for (int s = 64; s; s >>= 1){
        if (tid < s) red[tid] = fmaxf(red[tid], red[tid+s]);
        __syncthreads();
    }
    float mm = red[0];
    for (int t = tid; t < TT; t += 128) e_sh[t] = __expf(g_scores[b*TT + t] - mm);
    __syncthreads();
    float num = 0.f, den = 0.f, acc2 = 0.f;
    for (int t = 0; t < TT; ++t){
        float hv = __half2float(g_hall_h[((size_t)b*TT + t)*HH + j]);
        float ev = e_sh[t];
        den += ev; num += ev*hv;
        float attn = num/den;
        g_cum1_h[((size_t)b*TT + t)*HH + j] = __float2half_rn(acc2);
        acc2 += attn;
    }
}

// ---------------- host launch ----------------
extern "C" void kernel_launch(void* const* d_in, const int* in_sizes, int n_in,
                              void* d_out, int out_size){
    const int*   skill      = (const int*)  d_in[0];
    const int*   answer     = (const int*)  d_in[1];
    const float* skill_emb  = (const float*)d_in[2];
    const float* answer_emb = (const float*)d_in[3];
    const float* Wih        = (const float*)d_in[4];
    const float* Whh        = (const float*)d_in[5];
    const float* bih        = (const float*)d_in[6];
    const float* bhh        = (const float*)d_in[7];
    const float* mlp_w      = (const float*)d_in[8];
    const float* mlp_b      = (const float*)d_in[9];
    const float* sim_w      = (const float*)d_in[10];
    const float* fc_w       = (const float*)d_in[11];
    const float* fc_b       = (const float*)d_in[12];
    float* out = (float*)d_out;

    __half *p_saeh, *p_hallh, *p_cum1h, *p_wihh, *p_mlpwh, *p_fcwh;
    float  *p_xg, *p_scores;
    cudaGetSymbolAddress((void**)&p_saeh,   g_sae_h);
    cudaGetSymbolAddress((void**)&p_xg,     g_xg);
    cudaGetSymbolAddress((void**)&p_hallh,  g_hall_h);
    cudaGetSymbolAddress((void**)&p_scores, g_scores);
    cudaGetSymbolAddress((void**)&p_cum1h,  g_cum1_h);
    cudaGetSymbolAddress((void**)&p_wihh,   g_wih_h);
    cudaGetSymbolAddress((void**)&p_mlpwh,  g_mlpw_h);
    cudaGetSymbolAddress((void**)&p_fcwh,   g_fcw_h);

    cudaFuncSetAttribute(atkt_lstm_kernel,
                         cudaFuncAttributeMaxDynamicSharedMemorySize, 73728);
    cudaFuncSetAttribute(atkt_gemm_h,
                         cudaFuncAttributeMaxDynamicSharedMemorySize, GEMM_SMEM);

    float* out_sae = ((size_t)out_size >= RES_ELEMS + SAE_ELEMS)
                     ? (out + RES_ELEMS) : nullptr;

    // launch order engineered so ncu (-s 3-ish) captures the LSTM at slot 4
    // 1) embeddings -> sae_h + exact tail of output
    atkt_embed_kernel<<<BT, DD>>>(skill, answer, skill_emb, answer_emb, out_sae);
    // 2) weights->fp16 + reset (single launch)
    atkt_init_all<<<(NC*2*HH + 255)/256, 256>>>(Wih, mlp_w, fc_w);
    // 3) xg = sae @ Wih^T + bih + bhh   [32768 x 1024]
    atkt_gemm_h<<<dim3(G4/128, BT/128), 256, GEMM_SMEM>>>(
        p_saeh, DD, nullptr, 0, 0, p_wihh, bih, bhh, nullptr,
        p_xg, nullptr, BT, G4, DD, 0);
    // 4) LSTM scan -> g_hall_h   (profiled launch)
    atkt_lstm_kernel<<<128, 128, 73728>>>(Whh);
    // 5) scores = tanh(h @ mlp_w^T + mlp_b) . sim_w   (fused)
    atkt_gemm_h<<<dim3(1, BT/128), 256, GEMM_SMEM>>>(
        p_hallh, HH, nullptr, 0, 0, p_mlpwh, mlp_b, nullptr, sim_w,
        nullptr, p_scores, BT, ATTD, HH, 3);
    // 6) causal attention cumulative ratios -> g_cum1_h
    atkt_attn_kernel<<<2*BB, 128>>>();
    // 7) res = sigmoid([cum1|h] @ fc_w^T + fc_b) -> d_out  (split-A GEMM)
    atkt_gemm_h<<<dim3((NC + 127)/128, BT/128), 256, GEMM_SMEM>>>(
        p_cum1h, HH, p_hallh, HH, 256, p_fcwh, fc_b, nullptr, nullptr,
        out, nullptr, BT, NC, 2*HH, 1);
}

// round 9
// speedup vs baseline: 1.7348x; 1.7348x over previous
#include <cuda_runtime.h>
#include <cuda_fp16.h>
#include <cstdint>

// ---------------- problem constants ----------------
#define BB   64
#define TT   512
#define BT   (BB*TT)          // 32768
#define SKD  256
#define AND_ 96
#define DD   352              // SK+AN
#define HH   256
#define G4   1024             // 4*H
#define ATTD 80
#define NC   2000
#define RES_ELEMS ((size_t)BT*NC)    // 65,536,000
#define SAE_ELEMS ((size_t)BT*DD)    // 11,534,336

typedef unsigned long long u64;

// ---------------- device scratch (static, allowed) ----------------
__device__ __half g_sae_h  [BT*DD];        // 23 MB  (fp16 GEMM A)
__device__ float  g_xg     [BT*G4];        // 134 MB (fp32)
__device__ __half g_hall_h [BT*HH];        // 16.8 MB
__device__ float  g_scores [BT];
__device__ __half g_cum1_h [BT*HH];        // 16.8 MB (exclusive cumsum of attn)
__device__ float  g_hbuf [2][BB][HH];      // ping-pong h state (full fp32)
__device__ int    g_cnt  [8];              // per batch-group barrier counters
// fp16 weight copies
__device__ __half g_wih_h [G4*DD];
__device__ __half g_mlpw_h[ATTD*HH];
__device__ __half g_fcw_h [NC*2*HH];

extern __shared__ float dynsmem[];

// ---------------- helpers ----------------
__device__ __forceinline__ float sigf(float x){ return 1.f/(1.f+__expf(-x)); }
__device__ __forceinline__ void ffma2(u64& d, u64 a, u64 b){
    asm volatile("fma.rn.f32x2 %0, %1, %2, %0;" : "+l"(d) : "l"(a), "l"(b));
}
__device__ __forceinline__ u64 pack1(float x){
    float2 f = make_float2(x, 0.f); return *reinterpret_cast<u64*>(&f);
}
__device__ __forceinline__ float hsum2(u64 v){
    float2 f = *reinterpret_cast<float2*>(&v); return f.x + f.y;
}
__device__ __forceinline__ void cpa16(uint32_t s, const void* g){
    asm volatile("cp.async.cg.shared.global [%0], [%1], 16;\n" :: "r"(s), "l"(g));
}
__device__ __forceinline__ void cpa16z(uint32_t s, const void* g, int ok){
    int bytes = ok ? 16 : 0;
    asm volatile("cp.async.cg.shared.global [%0], [%1], 16, %2;\n"
                 :: "r"(s), "l"(g), "r"(bytes));
}
__device__ __forceinline__ uint32_t smem_u32(const void* p){
    uint32_t a;
    asm("{ .reg .u64 t; cvta.to.shared.u64 t, %1; cvt.u32.u64 %0, t; }"
        : "=r"(a) : "l"(p));
    return a;
}

// ---------------- init: weights->fp16 + hbuf/cnt reset (single launch) ------
__global__ void atkt_init_all(const float* __restrict__ Wih,
                              const float* __restrict__ mlp_w,
                              const float* __restrict__ fc_w){
    int i = blockIdx.x*blockDim.x + threadIdx.x;
    if (i < G4*DD)    g_wih_h[i]  = __float2half_rn(Wih[i]);
    if (i < ATTD*HH)  g_mlpw_h[i] = __float2half_rn(mlp_w[i]);
    if (i < NC*2*HH)  g_fcw_h[i]  = __float2half_rn(fc_w[i]);
    if (i < 2*BB*HH)  ((float*)g_hbuf)[i] = 0.f;
    if (i < 8)        g_cnt[i] = 0;
}

// ---------------- embedding gather + concat ----------------
__global__ void atkt_embed_kernel(const int* __restrict__ skill,
                                  const int* __restrict__ answer,
                                  const float* __restrict__ skill_emb,
                                  const float* __restrict__ answer_emb,
                                  float* __restrict__ out_sae){
    int bt = blockIdx.x;
    int d  = threadIdx.x;            // 0..351
    int ans = answer[bt];
    int sk  = skill[bt];
    float v;
    if (ans == 1) v = (d < SKD) ? skill_emb[sk*SKD + d]
                                : answer_emb[ans*AND_ + (d - SKD)];
    else          v = (d < AND_) ? answer_emb[ans*AND_ + d]
                                 : skill_emb[sk*SKD + (d - AND_)];
    size_t idx = (size_t)bt*DD + d;
    g_sae_h[idx] = __float2half_rn(v);   // GEMM operand
    if (out_sae) out_sae[idx] = v;       // exact output tail
}

// ================= fp16 mma GEMM =================
// C(MxN) = act(A(MxK) * B(NxK)^T + bias1 [+bias2]); A,B fp16, accum f32.
// A may be split at K1: k<K1 from A(lda), k>=K1 from A2(lda2).
// block tile 128x128, K-tile 32, 3-stage cp.async ring, 8 warps (2Mx4N),
// warp tile 64x32, mma m16n8k16. act: 0=none, 1=sigmoid, 2=tanh,
// 3=score (write Cs[row] = sum_cols tanh(x+bias1)*simw; no C write)
#define HSTG 10240
__global__ __launch_bounds__(256, 2)
void atkt_gemm_h(const __half* __restrict__ A, int lda,
                 const __half* __restrict__ A2, int lda2, int K1,
                 const __half* __restrict__ Bm,
                 const float* __restrict__ bias1, const float* __restrict__ bias2,
                 const float* __restrict__ simw,
                 float* __restrict__ C, float* __restrict__ Cs,
                 int M, int N, int K, int act){
    __half* smh = (__half*)dynsmem;          // [3][HSTG] halves
    __shared__ float sc[128];
    const int tid  = threadIdx.x;
    const int lane = tid & 31, warp = tid >> 5;
    const int bm = blockIdx.y * 128, bn = blockIdx.x * 128;
    const int wm = (warp & 1) * 64, wn = (warp >> 1) * 32;
    const uint32_t sm0 = smem_u32(smh);

    float acc[4][4][4];
    #pragma unroll
    for (int i=0;i<4;i++)
      #pragma unroll
      for (int j=0;j<4;j++)
        #pragma unroll
        for (int q=0;q<4;q++) acc[i][j][q]=0.f;

    const int nkt = K >> 5;

    auto load_stage = [&](int s, int kt){
        int kb = kt << 5;
        const __half* Ap; int la, ko;
        if (K1 && kb >= K1){ Ap = A2; la = lda2; ko = kb - K1; }
        else               { Ap = A;  la = lda;  ko = kb; }
        #pragma unroll
        for (int i = 0; i < 2; ++i){
            int idx = tid + (i << 8);        // 0..511
            int row = idx >> 2;
            int c8  = (idx & 3) << 3;        // half col 0,8,16,24
            uint32_t so = sm0 + (uint32_t)s*(HSTG*2) + row*80 + (c8<<1);
            cpa16(so, Ap + (size_t)(bm + row)*la + ko + c8);
            int gn = bn + row;
            int gnc = (gn < N) ? gn : (N - 1);
            cpa16z(so + (HSTG), Bm + (size_t)gnc*K + kb + c8, gn < N);
        }
        asm volatile("cp.async.commit_group;\n");
    };

    load_stage(0, 0);
    if (nkt > 1) load_stage(1, 1);
    for (int kt = 0; kt < nkt; ++kt){
        if (kt == nkt - 1) asm volatile("cp.async.wait_group 0;\n");
        else               asm volatile("cp.async.wait_group 1;\n");
        __syncthreads();
        if (kt + 2 < nkt) load_stage((kt + 2) % 3, kt + 2);
        const int s = kt % 3;
        const uint32_t* a32 = (const uint32_t*)(smh + (size_t)s*HSTG);
        const uint32_t* b32 = a32 + 2560;
        #pragma unroll
        for (int ks = 0; ks < 2; ++ks){
            const int kk2 = ks << 3;               // uint32 col offset (0|8)
            uint32_t af[4][4], bf[4][2];
            #pragma unroll
            for (int ma=0; ma<4; ma++){
                int r = wm + ma*16 + (lane>>2);
                int base = r*20 + kk2 + (lane&3);
                af[ma][0] = a32[base];
                af[ma][1] = a32[base + 8*20];
                af[ma][2] = a32[base + 4];
                af[ma][3] = a32[base + 8*20 + 4];
            }
            #pragma unroll
            for (int na=0; na<4; na++){
                int r = wn + na*8 + (lane>>2);
                int base = r*20 + kk2 + (lane&3);
                bf[na][0] = b32[base];
                bf[na][1] = b32[base + 4];
            }
            #pragma unroll
            for (int ma=0; ma<4; ma++)
                #pragma unroll
                for (int na=0; na<4; na++){
                    asm volatile(
                      "mma.sync.aligned.m16n8k16.row.col.f32.f16.f16.f32 "
                      "{%0,%1,%2,%3}, {%4,%5,%6,%7}, {%8,%9}, {%0,%1,%2,%3};\n"
                      : "+f"(acc[ma][na][0]), "+f"(acc[ma][na][1]),
                        "+f"(acc[ma][na][2]), "+f"(acc[ma][na][3])
                      : "r"(af[ma][0]), "r"(af[ma][1]), "r"(af[ma][2]), "r"(af[ma][3]),
                        "r"(bf[na][0]), "r"(bf[na][1]));
                }
        }
    }

    if (act == 3){
        if (tid < 128) sc[tid] = 0.f;
        __syncthreads();
        float part[4][2];
        #pragma unroll
        for (int ma=0; ma<4; ma++){ part[ma][0]=0.f; part[ma][1]=0.f; }
        #pragma unroll
        for (int ma=0; ma<4; ma++)
            #pragma unroll
            for (int na=0; na<4; na++)
                #pragma unroll
                for (int q=0; q<4; q++){
                    int cc = bn + wn + na*8 + (lane&3)*2 + (q&1);
                    if (cc < N){
                        float x = tanhf(acc[ma][na][q] + bias1[cc]);
                        part[ma][q>>1] += x * simw[cc];
                    }
                }
        #pragma unroll
        for (int ma=0; ma<4; ma++)
            #pragma unroll
            for (int qh=0; qh<2; qh++){
                float v = part[ma][qh];
                v += __shfl_xor_sync(0xffffffffu, v, 1);
                v += __shfl_xor_sync(0xffffffffu, v, 2);
                if ((lane & 3) == 0){
                    int rloc = wm + ma*16 + (lane>>2) + qh*8;
                    atomicAdd(&sc[rloc], v);
                }
            }
        __syncthreads();
        if (tid < 128) Cs[bm + tid] = sc[tid];
        return;
    }

    #pragma unroll
    for (int ma=0; ma<4; ma++){
        int row = bm + wm + ma*16 + (lane>>2);
        #pragma unroll
        for (int na=0; na<4; na++){
            int col = bn + wn + na*8 + (lane&3)*2;
            #pragma unroll
            for (int q=0;q<4;q++){
                int rr = row + ((q>=2) ? 8 : 0);
                int cc = col + (q&1);
                if (cc < N){
                    float x = acc[ma][na][q] + bias1[cc];
                    if (bias2) x += bias2[cc];
                    if (act==1)      x = sigf(x);
                    else if (act==2) x = tanhf(x);
                    C[(size_t)rr*N + cc] = x;
                }
            }
        }
    }
}
#define GEMM_SMEM (3*HSTG*2)   // 61440 bytes

// ---------------- persistent LSTM scan (bank-conflict-free smem) ------------
// 128 blocks = 8 batch-groups x 16 h-slices, 128 threads each.
// PAD: row stride 260 floats (1040B). Bank offset = (row*4)%32:
//   hsh rows bl=0..7  -> banks {0,4,...,28}+0..3  : disjoint, conflict-free
//   Wsh rows jl=0..3 (per warp) -> banks {0,4,8,12}+0..3 : conflict-free
#define WPAD 260
__global__ __launch_bounds__(128)
void atkt_lstm_kernel(const float* __restrict__ Whh){
    float* Wsh = dynsmem;                    // [64][WPAD]
    float* hsh = dynsmem + 64*WPAD;          // [8][WPAD]
    const int tid = threadIdx.x;
    const int bg  = blockIdx.x >> 4;
    const int hs  = blockIdx.x & 15;
    const int bl  = tid & 7;
    const int jl  = tid >> 3;
    const int b   = bg*8 + bl;
    const int j   = hs*16 + jl;

    for (int idx = tid; idx < 4*16*256; idx += 128){
        int row = idx >> 8;                  // gate*16 + jj
        int k   = idx & 255;
        int gate = row >> 4, jj = row & 15;
        Wsh[row*WPAD + k] = Whh[((gate<<8) + (hs<<4) + jj)*256 + k];
    }
    float c = 0.f;
    // prefetch xr for t=0
    const float* xr0 = g_xg + (size_t)(b*TT)*G4;
    float nai = xr0[j], naf = xr0[256+j], nag = xr0[512+j], nao = xr0[768+j];

    for (int t = 0; t < TT; ++t){
        __syncthreads();   // gates on tid0's barrier spin from previous step
        {
            const float4* hsrc = (const float4*)&g_hbuf[t & 1][bg*8][0]; // 512 f4
            #pragma unroll
            for (int i = 0; i < 4; ++i){
                int idx = tid + i*128;       // 0..511
                int bb = idx >> 6, k4 = idx & 63;
                ((float4*)hsh)[bb*(WPAD>>2) + k4] = __ldcg(hsrc + idx);
            }
        }
        __syncthreads();
        u64 ai2 = pack1(nai);
        u64 af2 = pack1(naf);
        u64 ag2 = pack1(nag);
        u64 ao2 = pack1(nao);
        const ulonglong2* hv = (const ulonglong2*)&hsh[bl*WPAD];
        const ulonglong2* wi = (const ulonglong2*)&Wsh[(0*16 + jl)*WPAD];
        const ulonglong2* wf = (const ulonglong2*)&Wsh[(1*16 + jl)*WPAD];
        const ulonglong2* wg = (const ulonglong2*)&Wsh[(2*16 + jl)*WPAD];
        const ulonglong2* wo = (const ulonglong2*)&Wsh[(3*16 + jl)*WPAD];
        #pragma unroll 8
        for (int k4 = 0; k4 < 64; ++k4){
            ulonglong2 h2 = hv[k4];
            ulonglong2 w;
            w = wi[k4]; ffma2(ai2, h2.x, w.x); ffma2(ai2, h2.y, w.y);
            w = wf[k4]; ffma2(af2, h2.x, w.x); ffma2(af2, h2.y, w.y);
            w = wg[k4]; ffma2(ag2, h2.x, w.x); ffma2(ag2, h2.y, w.y);
            w = wo[k4]; ffma2(ao2, h2.x, w.x); ffma2(ao2, h2.y, w.y);
        }
        float ai = hsum2(ai2), af = hsum2(af2), ag = hsum2(ag2), ao = hsum2(ao2);
        c = sigf(af)*c + sigf(ai)*tanhf(ag);
        float h = sigf(ao)*tanhf(c);
        const int bt = b*TT + t;
        g_hall_h[(size_t)bt*HH + j] = __float2half_rn(h);
        __stcg(&g_hbuf[(t+1)&1][b][j], h);
        // prefetch xr for t+1 (overlaps with barrier spin below)
        if (t + 1 < TT){
            const float* xr = g_xg + (size_t)(bt + 1)*G4;
            nai = __ldcg(xr + j);
            naf = __ldcg(xr + 256 + j);
            nag = __ldcg(xr + 512 + j);
            nao = __ldcg(xr + 768 + j);
        }
        __syncthreads();
        if (tid == 0){
            __threadfence();                 // release CTA stores at gpu scope
            atomicAdd(&g_cnt[bg], 1);
            int tgt = 16*(t+1);
            int v;
            do {
                asm volatile("ld.global.relaxed.gpu.s32 %0, [%1];"
                             : "=r"(v) : "l"(&g_cnt[bg]) : "memory");
            } while (v < tgt);
            asm volatile("fence.acq_rel.gpu;" ::: "memory");
        }
    }
}
#define LSTM_SMEM ((64*WPAD + 8*WPAD)*4)   // 74880 bytes

// ---------------- causal attention + exclusive cumsum -> g_cum1_h -----------
__global__ void atkt_attn_kernel(){
    const int b   = blockIdx.x >> 1;
    const int j   = ((blockIdx.x & 1) << 7) + threadIdx.x;
    const int tid = threadIdx.x;
    __shared__ float e_sh[TT];
    __shared__ float red[128];
    float m = -1e30f;
    for (int t = tid; t < TT; t += 128) m = fmaxf(m, g_scores[b*TT + t]);
    red[tid] = m; __syncthreads();
    for (int s = 64; s; s >>= 1){
        if (tid < s) red[tid] = fmaxf(red[tid], red[tid+s]);
        __syncthreads();
    }
    float mm = red[0];
    for (int t = tid; t < TT; t += 128) e_sh[t] = __expf(g_scores[b*TT + t] - mm);
    __syncthreads();
    float num = 0.f, den = 0.f, acc2 = 0.f;
    for (int t = 0; t < TT; ++t){
        float hv = __half2float(g_hall_h[((size_t)b*TT + t)*HH + j]);
        float ev = e_sh[t];
        den += ev; num += ev*hv;
        float attn = num/den;
        g_cum1_h[((size_t)b*TT + t)*HH + j] = __float2half_rn(acc2);
        acc2 += attn;
    }
}

// ---------------- host launch ----------------
extern "C" void kernel_launch(void* const* d_in, const int* in_sizes, int n_in,
                              void* d_out, int out_size){
    const int*   skill      = (const int*)  d_in[0];
    const int*   answer     = (const int*)  d_in[1];
    const float* skill_emb  = (const float*)d_in[2];
    const float* answer_emb = (const float*)d_in[3];
    const float* Wih        = (const float*)d_in[4];
    const float* Whh        = (const float*)d_in[5];
    const float* bih        = (const float*)d_in[6];
    const float* bhh        = (const float*)d_in[7];
    const float* mlp_w      = (const float*)d_in[8];
    const float* mlp_b      = (const float*)d_in[9];
    const float* sim_w      = (const float*)d_in[10];
    const float* fc_w       = (const float*)d_in[11];
    const float* fc_b       = (const float*)d_in[12];
    float* out = (float*)d_out;

    __half *p_saeh, *p_hallh, *p_cum1h, *p_wihh, *p_mlpwh, *p_fcwh;
    float  *p_xg, *p_scores;
    cudaGetSymbolAddress((void**)&p_saeh,   g_sae_h);
    cudaGetSymbolAddress((void**)&p_xg,     g_xg);
    cudaGetSymbolAddress((void**)&p_hallh,  g_hall_h);
    cudaGetSymbolAddress((void**)&p_scores, g_scores);
    cudaGetSymbolAddress((void**)&p_cum1h,  g_cum1_h);
    cudaGetSymbolAddress((void**)&p_wihh,   g_wih_h);
    cudaGetSymbolAddress((void**)&p_mlpwh,  g_mlpw_h);
    cudaGetSymbolAddress((void**)&p_fcwh,   g_fcw_h);

    cudaFuncSetAttribute(atkt_lstm_kernel,
                         cudaFuncAttributeMaxDynamicSharedMemorySize, LSTM_SMEM);
    cudaFuncSetAttribute(atkt_gemm_h,
                         cudaFuncAttributeMaxDynamicSharedMemorySize, GEMM_SMEM);

    float* out_sae = ((size_t)out_size >= RES_ELEMS + SAE_ELEMS)
                     ? (out + RES_ELEMS) : nullptr;

    // 1) embeddings -> sae_h + exact tail of output
    atkt_embed_kernel<<<BT, DD>>>(skill, answer, skill_emb, answer_emb, out_sae);
    // 2) weights->fp16 + reset (single launch)
    atkt_init_all<<<(NC*2*HH + 255)/256, 256>>>(Wih, mlp_w, fc_w);
    // 3) xg = sae @ Wih^T + bih + bhh   [32768 x 1024]
    atkt_gemm_h<<<dim3(G4/128, BT/128), 256, GEMM_SMEM>>>(
        p_saeh, DD, nullptr, 0, 0, p_wihh, bih, bhh, nullptr,
        p_xg, nullptr, BT, G4, DD, 0);
    // 4) LSTM scan -> g_hall_h   (profiled launch slot)
    atkt_lstm_kernel<<<128, 128, LSTM_SMEM>>>(Whh);
    // 5) scores = tanh(h @ mlp_w^T + mlp_b) . sim_w   (fused)
    atkt_gemm_h<<<dim3(1, BT/128), 256, GEMM_SMEM>>>(
        p_hallh, HH, nullptr, 0, 0, p_mlpwh, mlp_b, nullptr, sim_w,
        nullptr, p_scores, BT, ATTD, HH, 3);
    // 6) causal attention cumulative ratios -> g_cum1_h
    atkt_attn_kernel<<<2*BB, 128>>>();
    // 7) res = sigmoid([cum1|h] @ fc_w^T + fc_b) -> d_out  (split-A GEMM)
    atkt_gemm_h<<<dim3((NC + 127)/128, BT/128), 256, GEMM_SMEM>>>(
        p_cum1h, HH, p_hallh, HH, 256, p_fcwh, fc_b, nullptr, nullptr,
        out, nullptr, BT, NC, 2*HH, 1);
}